// round 6
// baseline (speedup 1.0000x reference)
#include <cuda_runtime.h>
#include <cstdint>

#define NN 50000
#define EE 600000
#define HH 4
#define HO 128
#define IND 128
#define EFD 64

// ---------------- device scratch (no cudaMalloc allowed) ----------------
__device__ float g_feat[NN * HO];   // GATv2 shared projection
__device__ float g_res[NN * HO];    // residual projection
__device__ float g_h[NN * HO];      // relu(rst/denom + res)
__device__ float g_denom[NN * HH];  // attention softmax denom (unnormalized)
__device__ float g_rst[NN * HO];    // UNNORMALIZED attention-weighted aggregation
__device__ float g_den2[NN * HO];   // mailbox denom
__device__ float g_num2[NN * HO];   // mailbox numer

typedef unsigned long long ull;

__device__ __forceinline__ void ffma2(ull& d, ull a, ull b) {
    asm("fma.rn.f32x2 %0, %1, %2, %0;" : "+l"(d) : "l"(a), "l"(b));
}
__device__ __forceinline__ ull dup2(float x) {
    ull r; asm("mov.b64 %0, {%1, %1};" : "=l"(r) : "f"(x)); return r;
}
__device__ __forceinline__ void unpack2(float& lo, float& hi, ull v) {
    asm("mov.b64 {%0, %1}, %2;" : "=f"(lo), "=f"(hi) : "l"(v));
}

__device__ __forceinline__ void red_add_v4(float* p, float a, float b, float c, float d) {
    asm volatile("red.global.add.v4.f32 [%0], {%1,%2,%3,%4};"
                 :: "l"(p), "f"(a), "f"(b), "f"(c), "f"(d) : "memory");
}

__device__ __forceinline__ float lrelu(float x) {
    return fmaxf(x, 0.2f * x);
}

// ---------------- init ----------------
__global__ void k_init() {
    int i = blockIdx.x * 256 + threadIdx.x;
    if (i < NN * HO) {
        g_rst[i] = 0.f;
        g_den2[i] = 0.f;
        g_num2[i] = 0.f;
    }
    if (i < NN * HH) g_denom[i] = 0.f;
}

// ---------------- node GEMM: feat = x@W^T + b ; res = x@Wres^T + bres ----------------
// 256 output cols (128 feat + 128 res), K = 128, 32 rows/chunk.
// Row-pair packed accumulators + fma.rn.f32x2 (2x FMA throughput).
#define NODE_LDW 260
#define NODE_LDR 34   // even pad: row-pair LDS.64 stays 8B-aligned
#define NODE_SMEM ((128 * NODE_LDW + 128 * NODE_LDR) * 4)
__global__ void __launch_bounds__(256) k_node_gemm(
    const float* __restrict__ x, const float* __restrict__ W, const float* __restrict__ b,
    const float* __restrict__ Wr, const float* __restrict__ br)
{
    extern __shared__ float sm[];
    float* sWT = sm;                     // [128 k][260 pad] (256 cols)
    float* sXT = sm + 128 * NODE_LDW;    // transposed rows: [128 k][34 pad] (32 rows)
    int t = threadIdx.x;
    for (int idx = t; idx < 256 * 128; idx += 256) {
        int j = idx >> 7, k = idx & 127;
        float v = (j < 128) ? W[j * 128 + k] : Wr[(j - 128) * 128 + k];
        sWT[k * NODE_LDW + j] = v;
    }
    __syncthreads();
    int tx = t & 63;   // cols 4*tx .. 4*tx+3 (of 256)
    int ty = t >> 6;   // rows ty*8 .. ty*8+7

    for (int r0 = blockIdx.x * 32; r0 < NN; r0 += gridDim.x * 32) {
        __syncthreads();
        int nrows = min(32, NN - r0);
        for (int idx = t; idx < nrows * 128; idx += 256) {
            int row = idx >> 7, col = idx & 127;
            sXT[col * NODE_LDR + row] = x[r0 * 128 + idx];
        }
        __syncthreads();

        ull acc[4][4];   // [row-pair][col]
        #pragma unroll
        for (int p = 0; p < 4; p++)
            #pragma unroll
            for (int j = 0; j < 4; j++) acc[p][j] = 0ull;

        #pragma unroll 2
        for (int k = 0; k < 128; k++) {
            float4 w4 = *(const float4*)&sWT[k * NODE_LDW + 4 * tx];
            ull wd0 = dup2(w4.x), wd1 = dup2(w4.y), wd2 = dup2(w4.z), wd3 = dup2(w4.w);
            const float* rb = &sXT[k * NODE_LDR + ty * 8];
            #pragma unroll
            for (int p = 0; p < 4; p++) {
                ull rp = *(const ull*)&rb[2 * p];   // rows (2p, 2p+1) packed
                ffma2(acc[p][0], wd0, rp);
                ffma2(acc[p][1], wd1, rp);
                ffma2(acc[p][2], wd2, rp);
                ffma2(acc[p][3], wd3, rp);
            }
        }

        int jc = 4 * tx;
        const float* bias = (jc < 128) ? b : br;
        float* outp = (jc < 128) ? g_feat : g_res;
        int jo = jc & 127;
        float4 bb = *(const float4*)&bias[jo];
        #pragma unroll
        for (int p = 0; p < 4; p++) {
            float lo[4], hi[4];
            #pragma unroll
            for (int j = 0; j < 4; j++) unpack2(lo[j], hi[j], acc[p][j]);
            int r = r0 + ty * 8 + 2 * p;
            if (r < NN) {
                float4 o = {lo[0] + bb.x, lo[1] + bb.y, lo[2] + bb.z, lo[3] + bb.w};
                *(float4*)&outp[r * 128 + jo] = o;
            }
            if (r + 1 < NN) {
                float4 o = {hi[0] + bb.x, hi[1] + bb.y, hi[2] + bb.z, hi[3] + bb.w};
                *(float4*)&outp[(r + 1) * 128 + jo] = o;
            }
        }
    }
}

// ---------------- FUSED attention: score + exp + denom + UNNORMALIZED rst scatter ----------------
// rst[d] accumulates ex * feat[src] (no alpha); k_relu divides by denom later.
// No max-shift: logits are tiny (|p| < ~2), exp never overflows; softmax exact up to rounding.
__global__ void __launch_bounds__(256) k_score_rst(
    const int* __restrict__ src, const int* __restrict__ dst, const float* __restrict__ attn)
{
    int gw = (blockIdx.x * 256 + threadIdx.x) >> 5;
    int lane = threadIdx.x & 31;
    int nw = (gridDim.x * 256) >> 5;
    for (int e = gw; e < EE; e += nw) {
        int s = src[e], d = dst[e];
        float4 fs = *(const float4*)&g_feat[s * 128 + lane * 4];
        float4 fd = *(const float4*)&g_feat[d * 128 + lane * 4];
        float4 av = *(const float4*)&attn[lane * 4];
        float p = lrelu(fs.x + fd.x) * av.x + lrelu(fs.y + fd.y) * av.y +
                  lrelu(fs.z + fd.z) * av.z + lrelu(fs.w + fd.w) * av.w;
        // reduce within each 8-lane head group; all 8 lanes end with the head sum
        p += __shfl_xor_sync(0xffffffffu, p, 1);
        p += __shfl_xor_sync(0xffffffffu, p, 2);
        p += __shfl_xor_sync(0xffffffffu, p, 4);
        float ex = __expf(p);
        if ((lane & 7) == 0)
            atomicAdd(&g_denom[d * 4 + (lane >> 3)], ex);
        red_add_v4(&g_rst[d * 128 + lane * 4],
                   ex * fs.x, ex * fs.y, ex * fs.z, ex * fs.w);
    }
}

// ---------------- h = relu(rst/denom + res) ----------------
// Guard denom==0 (nodes with no in-edges): rst=0 there, h = relu(res) with 0 contribution.
__global__ void __launch_bounds__(256) k_relu() {
    int i = blockIdx.x * 256 + threadIdx.x;
    if (i < NN * HO) {
        int node = i >> 7;
        int head = (i & 127) >> 5;
        float den = g_denom[node * 4 + head];
        float r = (den > 0.f) ? g_rst[i] / den : 0.f;
        g_h[i] = fmaxf(r + g_res[i], 0.f);
    }
}

// ---------------- FULLY FUSED edge pipeline ----------------
// e = ef@We^T + be ; m = h[src] + e ; ex = exp(m) ;
// den2[dst] += ex ; num2[dst] += ex*m.   (no max-shift, no m materialization)
// 128 cols, K = 64, 64 edges/chunk, fma.rn.f32x2 row-pair packed.
#define EDGE_LDW 132
#define EDGE_LDR 66   // even pad
#define EDGE_SMEM ((64 * EDGE_LDW + 64 * EDGE_LDR + 128) * 4)
__global__ void __launch_bounds__(256) k_edge_fused(
    const float* __restrict__ ef, const float* __restrict__ We, const float* __restrict__ be,
    const int* __restrict__ src, const int* __restrict__ dst)
{
    extern __shared__ float sm[];
    float* sWT = sm;                          // [64 k][132 pad] (128 cols)
    float* sXT = sm + 64 * EDGE_LDW;          // transposed: [64 k][66 pad] (64 edges)
    int*   ssrc = (int*)(sXT + 64 * EDGE_LDR);
    int*   sdst = ssrc + 64;
    int t = threadIdx.x;
    for (int idx = t; idx < 128 * 64; idx += 256) {
        int j = idx >> 6, k = idx & 63;
        sWT[k * EDGE_LDW + j] = We[j * 64 + k];
    }
    __syncthreads();
    int tx = t & 31;   // cols 4*tx .. 4*tx+3
    int ty = t >> 5;   // edges ty*8 .. ty*8+7

    for (int e0 = blockIdx.x * 64; e0 < EE; e0 += gridDim.x * 64) {
        __syncthreads();
        for (int idx = t; idx < 64 * 64; idx += 256) {
            int row = idx >> 6, col = idx & 63;
            sXT[col * EDGE_LDR + row] = ef[e0 * 64 + idx];
        }
        if (t < 64) {
            ssrc[t] = src[e0 + t];
            sdst[t] = dst[e0 + t];
        }
        __syncthreads();

        ull acc[4][4];   // [row-pair][col]
        #pragma unroll
        for (int p = 0; p < 4; p++)
            #pragma unroll
            for (int j = 0; j < 4; j++) acc[p][j] = 0ull;

        #pragma unroll 2
        for (int k = 0; k < 64; k++) {
            float4 w4 = *(const float4*)&sWT[k * EDGE_LDW + 4 * tx];
            ull wd0 = dup2(w4.x), wd1 = dup2(w4.y), wd2 = dup2(w4.z), wd3 = dup2(w4.w);
            const float* rb = &sXT[k * EDGE_LDR + ty * 8];
            #pragma unroll
            for (int p = 0; p < 4; p++) {
                ull rp = *(const ull*)&rb[2 * p];
                ffma2(acc[p][0], wd0, rp);
                ffma2(acc[p][1], wd1, rp);
                ffma2(acc[p][2], wd2, rp);
                ffma2(acc[p][3], wd3, rp);
            }
        }

        int jc = 4 * tx;
        float4 bb = *(const float4*)&be[jc];
        #pragma unroll
        for (int p = 0; p < 4; p++) {
            float lo[4], hi[4];
            #pragma unroll
            for (int j = 0; j < 4; j++) unpack2(lo[j], hi[j], acc[p][j]);
            #pragma unroll
            for (int half = 0; half < 2; half++) {
                int el = ty * 8 + 2 * p + half;
                int s = ssrc[el], d = sdst[el];
                float4 hv = *(const float4*)&g_h[s * 128 + jc];
                float m0 = (half ? hi[0] : lo[0]) + bb.x + hv.x;
                float m1 = (half ? hi[1] : lo[1]) + bb.y + hv.y;
                float m2 = (half ? hi[2] : lo[2]) + bb.z + hv.z;
                float m3 = (half ? hi[3] : lo[3]) + bb.w + hv.w;
                float ex0 = __expf(m0), ex1 = __expf(m1);
                float ex2 = __expf(m2), ex3 = __expf(m3);
                red_add_v4(&g_den2[d * 128 + jc], ex0, ex1, ex2, ex3);
                red_add_v4(&g_num2[d * 128 + jc], ex0 * m0, ex1 * m1, ex2 * m2, ex3 * m3);
            }
        }
    }
}

// ---------------- final output ----------------
__global__ void __launch_bounds__(256) k_out(float* __restrict__ out) {
    int i = blockIdx.x * 256 + threadIdx.x;
    if (i < NN * HO) {
        float den = g_den2[i];
        out[i] = (den > 0.f) ? g_num2[i] / den : 0.f;
    }
}

// ---------------- launch ----------------
extern "C" void kernel_launch(void* const* d_in, const int* in_sizes, int n_in,
                              void* d_out, int out_size)
{
    const float* node_feats = (const float*)d_in[0];
    const float* edge_feats = (const float*)d_in[1];
    const int*   src        = (const int*)d_in[2];
    const int*   dst        = (const int*)d_in[3];
    const float* W          = (const float*)d_in[4];
    const float* b          = (const float*)d_in[5];
    const float* attn_v     = (const float*)d_in[6];
    const float* Wres       = (const float*)d_in[7];
    const float* bres       = (const float*)d_in[8];
    const float* We         = (const float*)d_in[9];
    const float* be         = (const float*)d_in[10];
    float* out = (float*)d_out;

    cudaFuncSetAttribute(k_node_gemm, cudaFuncAttributeMaxDynamicSharedMemorySize, NODE_SMEM);
    cudaFuncSetAttribute(k_edge_fused, cudaFuncAttributeMaxDynamicSharedMemorySize, EDGE_SMEM);

    int nElem = NN * HO;
    int elemBlocks = (nElem + 255) / 256;
    int warpEdgeBlocks = (EE + 7) / 8;   // warp per edge, 8 warps/block

    k_init<<<elemBlocks, 256>>>();
    k_node_gemm<<<148, 256, NODE_SMEM>>>(node_feats, W, b, Wres, bres);
    k_score_rst<<<warpEdgeBlocks, 256>>>(src, dst, attn_v);
    k_relu<<<elemBlocks, 256>>>();
    k_edge_fused<<<592, 256, EDGE_SMEM>>>(edge_feats, We, be, src, dst);
    k_out<<<elemBlocks, 256>>>(out);
}

// round 8
// speedup vs baseline: 1.0493x; 1.0493x over previous
#include <cuda_runtime.h>
#include <cstdint>

#define NN 50000
#define EE 600000
#define HH 4
#define HO 128
#define IND 128
#define EFD 64

// ---------------- device scratch (no cudaMalloc allowed) ----------------
__device__ float g_feat[NN * HO];   // GATv2 shared projection
__device__ float g_res[NN * HO];    // residual projection
__device__ float g_h[NN * HO];      // relu(rst/denom + res)
__device__ float g_denom[NN * HH];  // attention softmax denom (unnormalized)
__device__ float g_rst[NN * HO];    // UNNORMALIZED attention-weighted aggregation
__device__ float g_den2[NN * HO];   // mailbox denom
__device__ float g_num2[NN * HO];   // mailbox numer

typedef unsigned long long ull;

__device__ __forceinline__ void ffma2(ull& d, ull a, ull b) {
    asm("fma.rn.f32x2 %0, %1, %2, %0;" : "+l"(d) : "l"(a), "l"(b));
}
__device__ __forceinline__ ull dup2(float x) {
    ull r; asm("mov.b64 %0, {%1, %1};" : "=l"(r) : "f"(x)); return r;
}
__device__ __forceinline__ void unpack2(float& lo, float& hi, ull v) {
    asm("mov.b64 {%0, %1}, %2;" : "=f"(lo), "=f"(hi) : "l"(v));
}

__device__ __forceinline__ void red_add_v4(float* p, float a, float b, float c, float d) {
    asm volatile("red.global.add.v4.f32 [%0], {%1,%2,%3,%4};"
                 :: "l"(p), "f"(a), "f"(b), "f"(c), "f"(d) : "memory");
}

__device__ __forceinline__ float lrelu(float x) {
    return fmaxf(x, 0.2f * x);
}

// ---------------- init A: zero rst + denom (needed before k_score_rst) ----------------
__global__ void k_init_a() {
    int i = blockIdx.x * 256 + threadIdx.x;
    if (i < NN * HO / 4) ((float4*)g_rst)[i] = make_float4(0.f, 0.f, 0.f, 0.f);
    if (i < NN * HH / 4) ((float4*)g_denom)[i] = make_float4(0.f, 0.f, 0.f, 0.f);
}

// ---------------- init B: zero den2 + num2 (needed before k_edge_fused) ----------------
__global__ void k_init_b() {
    int i = blockIdx.x * 256 + threadIdx.x;
    if (i < NN * HO / 4) {
        ((float4*)g_den2)[i] = make_float4(0.f, 0.f, 0.f, 0.f);
        ((float4*)g_num2)[i] = make_float4(0.f, 0.f, 0.f, 0.f);
    }
}

// ---------------- node GEMM: feat = x@W^T + b ; res = x@Wres^T + bres ----------------
// 256 output cols (128 feat + 128 res), K = 128, 32 rows/chunk.
// Row-pair packed accumulators + fma.rn.f32x2 (2x FMA throughput).
#define NODE_LDW 260
#define NODE_LDR 34   // even pad: row-pair LDS.64 stays 8B-aligned
#define NODE_SMEM ((128 * NODE_LDW + 128 * NODE_LDR) * 4)
__global__ void __launch_bounds__(256) k_node_gemm(
    const float* __restrict__ x, const float* __restrict__ W, const float* __restrict__ b,
    const float* __restrict__ Wr, const float* __restrict__ br)
{
    extern __shared__ float sm[];
    float* sWT = sm;                     // [128 k][260 pad] (256 cols)
    float* sXT = sm + 128 * NODE_LDW;    // transposed rows: [128 k][34 pad] (32 rows)
    int t = threadIdx.x;
    for (int idx = t; idx < 256 * 128; idx += 256) {
        int j = idx >> 7, k = idx & 127;
        float v = (j < 128) ? W[j * 128 + k] : Wr[(j - 128) * 128 + k];
        sWT[k * NODE_LDW + j] = v;
    }
    __syncthreads();
    int tx = t & 63;   // cols 4*tx .. 4*tx+3 (of 256)
    int ty = t >> 6;   // rows ty*8 .. ty*8+7

    for (int r0 = blockIdx.x * 32; r0 < NN; r0 += gridDim.x * 32) {
        __syncthreads();
        int nrows = min(32, NN - r0);
        for (int idx = t; idx < nrows * 128; idx += 256) {
            int row = idx >> 7, col = idx & 127;
            sXT[col * NODE_LDR + row] = x[r0 * 128 + idx];
        }
        __syncthreads();

        ull acc[4][4];   // [row-pair][col]
        #pragma unroll
        for (int p = 0; p < 4; p++)
            #pragma unroll
            for (int j = 0; j < 4; j++) acc[p][j] = 0ull;

        #pragma unroll 2
        for (int k = 0; k < 128; k++) {
            float4 w4 = *(const float4*)&sWT[k * NODE_LDW + 4 * tx];
            ull wd0 = dup2(w4.x), wd1 = dup2(w4.y), wd2 = dup2(w4.z), wd3 = dup2(w4.w);
            const float* rb = &sXT[k * NODE_LDR + ty * 8];
            #pragma unroll
            for (int p = 0; p < 4; p++) {
                ull rp = *(const ull*)&rb[2 * p];   // rows (2p, 2p+1) packed
                ffma2(acc[p][0], wd0, rp);
                ffma2(acc[p][1], wd1, rp);
                ffma2(acc[p][2], wd2, rp);
                ffma2(acc[p][3], wd3, rp);
            }
        }

        int jc = 4 * tx;
        const float* bias = (jc < 128) ? b : br;
        float* outp = (jc < 128) ? g_feat : g_res;
        int jo = jc & 127;
        float4 bb = *(const float4*)&bias[jo];
        #pragma unroll
        for (int p = 0; p < 4; p++) {
            float lo[4], hi[4];
            #pragma unroll
            for (int j = 0; j < 4; j++) unpack2(lo[j], hi[j], acc[p][j]);
            int r = r0 + ty * 8 + 2 * p;
            if (r < NN) {
                float4 o = {lo[0] + bb.x, lo[1] + bb.y, lo[2] + bb.z, lo[3] + bb.w};
                *(float4*)&outp[r * 128 + jo] = o;
            }
            if (r + 1 < NN) {
                float4 o = {hi[0] + bb.x, hi[1] + bb.y, hi[2] + bb.z, hi[3] + bb.w};
                *(float4*)&outp[(r + 1) * 128 + jo] = o;
            }
        }
    }
}

// ---------------- FUSED attention: score + exp + denom + UNNORMALIZED rst scatter ----------------
// rst[d] accumulates ex * feat[src] (no alpha); k_relu divides by denom later.
// No max-shift: logits are tiny (|p| < ~2), exp never overflows; softmax exact up to rounding.
__global__ void __launch_bounds__(256) k_score_rst(
    const int* __restrict__ src, const int* __restrict__ dst, const float* __restrict__ attn)
{
    int gw = (blockIdx.x * 256 + threadIdx.x) >> 5;
    int lane = threadIdx.x & 31;
    int nw = (gridDim.x * 256) >> 5;
    for (int e = gw; e < EE; e += nw) {
        int s = src[e], d = dst[e];
        float4 fs = *(const float4*)&g_feat[s * 128 + lane * 4];
        float4 fd = *(const float4*)&g_feat[d * 128 + lane * 4];
        float4 av = *(const float4*)&attn[lane * 4];
        float p = lrelu(fs.x + fd.x) * av.x + lrelu(fs.y + fd.y) * av.y +
                  lrelu(fs.z + fd.z) * av.z + lrelu(fs.w + fd.w) * av.w;
        // reduce within each 8-lane head group; all 8 lanes end with the head sum
        p += __shfl_xor_sync(0xffffffffu, p, 1);
        p += __shfl_xor_sync(0xffffffffu, p, 2);
        p += __shfl_xor_sync(0xffffffffu, p, 4);
        float ex = __expf(p);
        if ((lane & 7) == 0)
            atomicAdd(&g_denom[d * 4 + (lane >> 3)], ex);
        red_add_v4(&g_rst[d * 128 + lane * 4],
                   ex * fs.x, ex * fs.y, ex * fs.z, ex * fs.w);
    }
}

// ---------------- h = relu(rst/denom + res), float4 ----------------
// Guard denom==0 (nodes with no in-edges). One reciprocal per 4 elements.
__global__ void __launch_bounds__(256) k_relu() {
    int i4 = blockIdx.x * 256 + threadIdx.x;
    if (i4 < NN * HO / 4) {
        int base = i4 * 4;
        int node = base >> 7;
        int head = (base & 127) >> 5;   // 4-aligned chunk never crosses a 32-col head
        float den = g_denom[node * 4 + head];
        float rcp = (den > 0.f) ? 1.f / den : 0.f;
        float4 r = ((const float4*)g_rst)[i4];
        float4 s = ((const float4*)g_res)[i4];
        float4 o;
        o.x = fmaxf(r.x * rcp + s.x, 0.f);
        o.y = fmaxf(r.y * rcp + s.y, 0.f);
        o.z = fmaxf(r.z * rcp + s.z, 0.f);
        o.w = fmaxf(r.w * rcp + s.w, 0.f);
        ((float4*)g_h)[i4] = o;
    }
}

// ---------------- FULLY FUSED edge pipeline ----------------
// e = ef@We^T + be ; m = h[src] + e ; ex = exp(m) ;
// den2[dst] += ex ; num2[dst] += ex*m.   (no max-shift, no m materialization)
// 128 cols, K = 64, 64 edges/chunk, fma.rn.f32x2 row-pair packed.
#define EDGE_LDW 132
#define EDGE_LDR 66   // even pad
#define EDGE_SMEM ((64 * EDGE_LDW + 64 * EDGE_LDR + 128) * 4)
__global__ void __launch_bounds__(256) k_edge_fused(
    const float* __restrict__ ef, const float* __restrict__ We, const float* __restrict__ be,
    const int* __restrict__ src, const int* __restrict__ dst)
{
    extern __shared__ float sm[];
    float* sWT = sm;                          // [64 k][132 pad] (128 cols)
    float* sXT = sm + 64 * EDGE_LDW;          // transposed: [64 k][66 pad] (64 edges)
    int*   ssrc = (int*)(sXT + 64 * EDGE_LDR);
    int*   sdst = ssrc + 64;
    int t = threadIdx.x;
    for (int idx = t; idx < 128 * 64; idx += 256) {
        int j = idx >> 6, k = idx & 63;
        sWT[k * EDGE_LDW + j] = We[j * 64 + k];
    }
    __syncthreads();
    int tx = t & 31;   // cols 4*tx .. 4*tx+3
    int ty = t >> 5;   // edges ty*8 .. ty*8+7

    for (int e0 = blockIdx.x * 64; e0 < EE; e0 += gridDim.x * 64) {
        __syncthreads();
        for (int idx = t; idx < 64 * 64; idx += 256) {
            int row = idx >> 6, col = idx & 63;
            sXT[col * EDGE_LDR + row] = ef[e0 * 64 + idx];
        }
        if (t < 64) {
            ssrc[t] = src[e0 + t];
            sdst[t] = dst[e0 + t];
        }
        __syncthreads();

        ull acc[4][4];   // [row-pair][col]
        #pragma unroll
        for (int p = 0; p < 4; p++)
            #pragma unroll
            for (int j = 0; j < 4; j++) acc[p][j] = 0ull;

        #pragma unroll 2
        for (int k = 0; k < 64; k++) {
            float4 w4 = *(const float4*)&sWT[k * EDGE_LDW + 4 * tx];
            ull wd0 = dup2(w4.x), wd1 = dup2(w4.y), wd2 = dup2(w4.z), wd3 = dup2(w4.w);
            const float* rb = &sXT[k * EDGE_LDR + ty * 8];
            #pragma unroll
            for (int p = 0; p < 4; p++) {
                ull rp = *(const ull*)&rb[2 * p];
                ffma2(acc[p][0], wd0, rp);
                ffma2(acc[p][1], wd1, rp);
                ffma2(acc[p][2], wd2, rp);
                ffma2(acc[p][3], wd3, rp);
            }
        }

        int jc = 4 * tx;
        float4 bb = *(const float4*)&be[jc];
        #pragma unroll
        for (int p = 0; p < 4; p++) {
            float lo[4], hi[4];
            #pragma unroll
            for (int j = 0; j < 4; j++) unpack2(lo[j], hi[j], acc[p][j]);
            #pragma unroll
            for (int half = 0; half < 2; half++) {
                int el = ty * 8 + 2 * p + half;
                int s = ssrc[el], d = sdst[el];
                float4 hv = *(const float4*)&g_h[s * 128 + jc];
                float m0 = (half ? hi[0] : lo[0]) + bb.x + hv.x;
                float m1 = (half ? hi[1] : lo[1]) + bb.y + hv.y;
                float m2 = (half ? hi[2] : lo[2]) + bb.z + hv.z;
                float m3 = (half ? hi[3] : lo[3]) + bb.w + hv.w;
                float ex0 = __expf(m0), ex1 = __expf(m1);
                float ex2 = __expf(m2), ex3 = __expf(m3);
                red_add_v4(&g_den2[d * 128 + jc], ex0, ex1, ex2, ex3);
                red_add_v4(&g_num2[d * 128 + jc], ex0 * m0, ex1 * m1, ex2 * m2, ex3 * m3);
            }
        }
    }
}

// ---------------- final output, float4 ----------------
__global__ void __launch_bounds__(256) k_out(float* __restrict__ out) {
    int i4 = blockIdx.x * 256 + threadIdx.x;
    if (i4 < NN * HO / 4) {
        float4 num = ((const float4*)g_num2)[i4];
        float4 den = ((const float4*)g_den2)[i4];
        float4 o;
        o.x = (den.x > 0.f) ? __fdividef(num.x, den.x) : 0.f;
        o.y = (den.y > 0.f) ? __fdividef(num.y, den.y) : 0.f;
        o.z = (den.z > 0.f) ? __fdividef(num.z, den.z) : 0.f;
        o.w = (den.w > 0.f) ? __fdividef(num.w, den.w) : 0.f;
        ((float4*)out)[i4] = o;
    }
}

// ---------------- launch ----------------
extern "C" void kernel_launch(void* const* d_in, const int* in_sizes, int n_in,
                              void* d_out, int out_size)
{
    const float* node_feats = (const float*)d_in[0];
    const float* edge_feats = (const float*)d_in[1];
    const int*   src        = (const int*)d_in[2];
    const int*   dst        = (const int*)d_in[3];
    const float* W          = (const float*)d_in[4];
    const float* b          = (const float*)d_in[5];
    const float* attn_v     = (const float*)d_in[6];
    const float* Wres       = (const float*)d_in[7];
    const float* bres       = (const float*)d_in[8];
    const float* We         = (const float*)d_in[9];
    const float* be         = (const float*)d_in[10];
    float* out = (float*)d_out;

    cudaFuncSetAttribute(k_node_gemm, cudaFuncAttributeMaxDynamicSharedMemorySize, NODE_SMEM);
    cudaFuncSetAttribute(k_edge_fused, cudaFuncAttributeMaxDynamicSharedMemorySize, EDGE_SMEM);

    int vecBlocks = (NN * HO / 4 + 255) / 256;   // 6250
    int warpEdgeBlocks = (EE + 7) / 8;           // warp per edge, 8 warps/block

    // Launch order chosen so ncu's skip-5 capture (2 hidden harness launches +
    // 3 of ours) lands on k_score_rst — the highest-uncertainty kernel.
    k_init_a<<<vecBlocks, 256>>>();
    k_init_b<<<vecBlocks, 256>>>();
    k_node_gemm<<<148, 256, NODE_SMEM>>>(node_feats, W, b, Wres, bres);
    k_score_rst<<<warpEdgeBlocks, 256>>>(src, dst, attn_v);
    k_relu<<<vecBlocks, 256>>>();
    k_edge_fused<<<592, 256, EDGE_SMEM>>>(edge_feats, We, be, src, dst);
    k_out<<<vecBlocks, 256>>>(out);
}

// round 11
// speedup vs baseline: 1.0590x; 1.0092x over previous
#include <cuda_runtime.h>
#include <cstdint>

#define NN 50000
#define EE 600000
#define HH 4
#define HO 128
#define IND 128
#define EFD 64

// ---------------- device scratch (no cudaMalloc allowed) ----------------
__device__ float g_feat[NN * HO];   // GATv2 shared projection
__device__ float g_res[NN * HO];    // residual projection
__device__ float g_h[NN * HO];      // relu(attention-out + res)
__device__ float g_e[EE * HO];      // message m = edge_fc(ef) + be + h[src]
__device__ int   g_cnt[NN];         // in-degree
__device__ int   g_off[NN];         // CSR exclusive offsets
__device__ int   g_cur[NN];         // fill cursors
__device__ int   g_csr[EE];         // edge ids grouped by dst

typedef unsigned long long ull;

__device__ __forceinline__ void ffma2(ull& d, ull a, ull b) {
    asm("fma.rn.f32x2 %0, %1, %2, %0;" : "+l"(d) : "l"(a), "l"(b));
}
__device__ __forceinline__ ull dup2(float x) {
    ull r; asm("mov.b64 %0, {%1, %1};" : "=l"(r) : "f"(x)); return r;
}
__device__ __forceinline__ void unpack2(float& lo, float& hi, ull v) {
    asm("mov.b64 {%0, %1}, %2;" : "=f"(lo), "=f"(hi) : "l"(v));
}
__device__ __forceinline__ float lrelu(float x) {
    return fmaxf(x, 0.2f * x);
}

// ---------------- CSR build ----------------
__global__ void k_zero() {
    int i = blockIdx.x * 256 + threadIdx.x;
    if (i < NN) g_cnt[i] = 0;
}

__global__ void k_hist(const int* __restrict__ dst) {
    int e = blockIdx.x * 256 + threadIdx.x;
    if (e < EE) atomicAdd(&g_cnt[dst[e]], 1);
}

// single-block exclusive scan of g_cnt -> g_off (and g_cur copy)
__global__ void __launch_bounds__(1024) k_scan() {
    __shared__ int warpsum[32];
    __shared__ int carry;
    int t = threadIdx.x;
    int lane = t & 31, wid = t >> 5;
    if (t == 0) carry = 0;
    __syncthreads();
    for (int base = 0; base < NN; base += 1024) {
        int i = base + t;
        int v = (i < NN) ? g_cnt[i] : 0;
        int x = v;
        #pragma unroll
        for (int o = 1; o < 32; o <<= 1) {
            int y = __shfl_up_sync(0xffffffffu, x, o);
            if (lane >= o) x += y;
        }
        if (lane == 31) warpsum[wid] = x;
        __syncthreads();
        if (wid == 0) {
            int s = warpsum[lane];
            #pragma unroll
            for (int o = 1; o < 32; o <<= 1) {
                int y = __shfl_up_sync(0xffffffffu, s, o);
                if (lane >= o) s += y;
            }
            warpsum[lane] = s;
        }
        __syncthreads();
        int incl = x + (wid > 0 ? warpsum[wid - 1] : 0) + carry;
        if (i < NN) { g_off[i] = incl - v; g_cur[i] = incl - v; }
        __syncthreads();
        if (t == 1023) carry = incl;
        __syncthreads();
    }
}

__global__ void k_fill(const int* __restrict__ dst) {
    int e = blockIdx.x * 256 + threadIdx.x;
    if (e < EE) {
        int pos = atomicAdd(&g_cur[dst[e]], 1);
        g_csr[pos] = e;
    }
}

// ---------------- node GEMM: feat = x@W^T + b ; res = x@Wres^T + bres ----------------
// 256 output cols (128 feat + 128 res), K = 128, 32 rows/chunk.
// Row-pair packed accumulators + fma.rn.f32x2 (2x FMA throughput).
#define NODE_LDW 260
#define NODE_LDR 34   // even pad: row-pair LDS.64 stays 8B-aligned
#define NODE_SMEM ((128 * NODE_LDW + 128 * NODE_LDR) * 4)
__global__ void __launch_bounds__(256) k_node_gemm(
    const float* __restrict__ x, const float* __restrict__ W, const float* __restrict__ b,
    const float* __restrict__ Wr, const float* __restrict__ br)
{
    extern __shared__ float sm[];
    float* sWT = sm;                     // [128 k][260 pad] (256 cols)
    float* sXT = sm + 128 * NODE_LDW;    // transposed rows: [128 k][34 pad] (32 rows)
    int t = threadIdx.x;
    for (int idx = t; idx < 256 * 128; idx += 256) {
        int j = idx >> 7, k = idx & 127;
        float v = (j < 128) ? W[j * 128 + k] : Wr[(j - 128) * 128 + k];
        sWT[k * NODE_LDW + j] = v;
    }
    __syncthreads();
    int tx = t & 63;   // cols 4*tx .. 4*tx+3 (of 256)
    int ty = t >> 6;   // rows ty*8 .. ty*8+7

    for (int r0 = blockIdx.x * 32; r0 < NN; r0 += gridDim.x * 32) {
        __syncthreads();
        int nrows = min(32, NN - r0);
        for (int idx = t; idx < nrows * 128; idx += 256) {
            int row = idx >> 7, col = idx & 127;
            sXT[col * NODE_LDR + row] = x[r0 * 128 + idx];
        }
        __syncthreads();

        ull acc[4][4];   // [row-pair][col]
        #pragma unroll
        for (int p = 0; p < 4; p++)
            #pragma unroll
            for (int j = 0; j < 4; j++) acc[p][j] = 0ull;

        #pragma unroll 2
        for (int k = 0; k < 128; k++) {
            float4 w4 = *(const float4*)&sWT[k * NODE_LDW + 4 * tx];
            ull wd0 = dup2(w4.x), wd1 = dup2(w4.y), wd2 = dup2(w4.z), wd3 = dup2(w4.w);
            const float* rb = &sXT[k * NODE_LDR + ty * 8];
            #pragma unroll
            for (int p = 0; p < 4; p++) {
                ull rp = *(const ull*)&rb[2 * p];   // rows (2p, 2p+1) packed
                ffma2(acc[p][0], wd0, rp);
                ffma2(acc[p][1], wd1, rp);
                ffma2(acc[p][2], wd2, rp);
                ffma2(acc[p][3], wd3, rp);
            }
        }

        int jc = 4 * tx;
        const float* bias = (jc < 128) ? b : br;
        float* outp = (jc < 128) ? g_feat : g_res;
        int jo = jc & 127;
        float4 bb = *(const float4*)&bias[jo];
        #pragma unroll
        for (int p = 0; p < 4; p++) {
            float lo[4], hi[4];
            #pragma unroll
            for (int j = 0; j < 4; j++) unpack2(lo[j], hi[j], acc[p][j]);
            int r = r0 + ty * 8 + 2 * p;
            if (r < NN) {
                float4 o = {lo[0] + bb.x, lo[1] + bb.y, lo[2] + bb.z, lo[3] + bb.w};
                *(float4*)&outp[r * 128 + jo] = o;
            }
            if (r + 1 < NN) {
                float4 o = {hi[0] + bb.x, hi[1] + bb.y, hi[2] + bb.z, hi[3] + bb.w};
                *(float4*)&outp[(r + 1) * 128 + jo] = o;
            }
        }
    }
}

// ---------------- GATHER attention + h: warp per dst node ----------------
// For each in-edge: score from feat[src]+feat[dst], softmax-accumulate
// ex*feat[src] and ex in REGISTERS. Then h = relu(acc/den + res). No atomics.
// Fuses old k_score_rst + k_relu. No max-shift (logits tiny).
__global__ void __launch_bounds__(256) k_score_gather(
    const int* __restrict__ src, const float* __restrict__ attn)
{
    int w = (blockIdx.x * 256 + threadIdx.x) >> 5;
    if (w >= NN) return;
    int lane = threadIdx.x & 31;
    int d = w;

    float4 fd = *(const float4*)&g_feat[d * 128 + lane * 4];
    float4 av = *(const float4*)&attn[lane * 4];
    float4 acc = make_float4(0.f, 0.f, 0.f, 0.f);
    float den = 0.f;

    int beg = g_off[d], n = g_cnt[d];
    int s_next = (n > 0) ? src[g_csr[beg]] : 0;
    for (int i = 0; i < n; i++) {
        int s = s_next;
        if (i + 1 < n) s_next = src[g_csr[beg + i + 1]];
        float4 fs = *(const float4*)&g_feat[s * 128 + lane * 4];
        float p = lrelu(fs.x + fd.x) * av.x + lrelu(fs.y + fd.y) * av.y +
                  lrelu(fs.z + fd.z) * av.z + lrelu(fs.w + fd.w) * av.w;
        p += __shfl_xor_sync(0xffffffffu, p, 1);
        p += __shfl_xor_sync(0xffffffffu, p, 2);
        p += __shfl_xor_sync(0xffffffffu, p, 4);
        float ex = __expf(p);
        acc.x += ex * fs.x; acc.y += ex * fs.y;
        acc.z += ex * fs.z; acc.w += ex * fs.w;
        den += ex;
    }
    float rcp = (den > 0.f) ? 1.f / den : 0.f;
    float4 rv = *(const float4*)&g_res[d * 128 + lane * 4];
    float4 o;
    o.x = fmaxf(acc.x * rcp + rv.x, 0.f);
    o.y = fmaxf(acc.y * rcp + rv.y, 0.f);
    o.z = fmaxf(acc.z * rcp + rv.z, 0.f);
    o.w = fmaxf(acc.w * rcp + rv.w, 0.f);
    *(float4*)&g_h[d * 128 + lane * 4] = o;
}

// ---------------- edge GEMM + message store ----------------
// m = ef@We^T + be + h[src], stored to g_e. Plain STG epilogue (no atomics).
#define EDGE_LDW 132
#define EDGE_LDR 66   // even pad
#define EDGE_SMEM ((64 * EDGE_LDW + 64 * EDGE_LDR + 64) * 4)
__global__ void __launch_bounds__(256) k_edge_gemm(
    const float* __restrict__ ef, const float* __restrict__ We, const float* __restrict__ be,
    const int* __restrict__ src)
{
    extern __shared__ float sm[];
    float* sWT = sm;                          // [64 k][132 pad] (128 cols)
    float* sXT = sm + 64 * EDGE_LDW;          // transposed: [64 k][66 pad] (64 edges)
    int*   ssrc = (int*)(sXT + 64 * EDGE_LDR);
    int t = threadIdx.x;
    for (int idx = t; idx < 128 * 64; idx += 256) {
        int j = idx >> 6, k = idx & 63;
        sWT[k * EDGE_LDW + j] = We[j * 64 + k];
    }
    __syncthreads();
    int tx = t & 31;   // cols 4*tx .. 4*tx+3
    int ty = t >> 5;   // edges ty*8 .. ty*8+7

    for (int e0 = blockIdx.x * 64; e0 < EE; e0 += gridDim.x * 64) {
        __syncthreads();
        for (int idx = t; idx < 64 * 64; idx += 256) {
            int row = idx >> 6, col = idx & 63;
            sXT[col * EDGE_LDR + row] = ef[e0 * 64 + idx];
        }
        if (t < 64) ssrc[t] = src[e0 + t];
        __syncthreads();

        ull acc[4][4];   // [row-pair][col]
        #pragma unroll
        for (int p = 0; p < 4; p++)
            #pragma unroll
            for (int j = 0; j < 4; j++) acc[p][j] = 0ull;

        #pragma unroll 2
        for (int k = 0; k < 64; k++) {
            float4 w4 = *(const float4*)&sWT[k * EDGE_LDW + 4 * tx];
            ull wd0 = dup2(w4.x), wd1 = dup2(w4.y), wd2 = dup2(w4.z), wd3 = dup2(w4.w);
            const float* rb = &sXT[k * EDGE_LDR + ty * 8];
            #pragma unroll
            for (int p = 0; p < 4; p++) {
                ull rp = *(const ull*)&rb[2 * p];
                ffma2(acc[p][0], wd0, rp);
                ffma2(acc[p][1], wd1, rp);
                ffma2(acc[p][2], wd2, rp);
                ffma2(acc[p][3], wd3, rp);
            }
        }

        int jc = 4 * tx;
        float4 bb = *(const float4*)&be[jc];
        #pragma unroll
        for (int p = 0; p < 4; p++) {
            float lo[4], hi[4];
            #pragma unroll
            for (int j = 0; j < 4; j++) unpack2(lo[j], hi[j], acc[p][j]);
            #pragma unroll
            for (int half = 0; half < 2; half++) {
                int el = ty * 8 + 2 * p + half;
                int eid = e0 + el;
                int s = ssrc[el];
                float4 hv = *(const float4*)&g_h[s * 128 + jc];
                float4 m;
                m.x = (half ? hi[0] : lo[0]) + bb.x + hv.x;
                m.y = (half ? hi[1] : lo[1]) + bb.y + hv.y;
                m.z = (half ? hi[2] : lo[2]) + bb.z + hv.z;
                m.w = (half ? hi[3] : lo[3]) + bb.w + hv.w;
                *(float4*)&g_e[eid * 128 + jc] = m;
            }
        }
    }
}

// ---------------- GATHER mailbox softmax + output: warp per dst node ----------------
// Register accumulation of exp-sums over the dst's in-edges; writes out directly.
// Fuses old k_edge scatter + k_out. No atomics.
__global__ void __launch_bounds__(256) k_mail_gather(float* __restrict__ out) {
    int w = (blockIdx.x * 256 + threadIdx.x) >> 5;
    if (w >= NN) return;
    int lane = threadIdx.x & 31;
    int d = w;

    float4 den = make_float4(0.f, 0.f, 0.f, 0.f);
    float4 num = make_float4(0.f, 0.f, 0.f, 0.f);

    int beg = g_off[d], n = g_cnt[d];
    int e_next = (n > 0) ? g_csr[beg] : 0;
    for (int i = 0; i < n; i++) {
        int e = e_next;
        if (i + 1 < n) e_next = g_csr[beg + i + 1];
        float4 m = *(const float4*)&g_e[e * 128 + lane * 4];
        float ex0 = __expf(m.x), ex1 = __expf(m.y);
        float ex2 = __expf(m.z), ex3 = __expf(m.w);
        den.x += ex0; den.y += ex1; den.z += ex2; den.w += ex3;
        num.x += ex0 * m.x; num.y += ex1 * m.y;
        num.z += ex2 * m.z; num.w += ex3 * m.w;
    }
    float4 o;
    o.x = (den.x > 0.f) ? __fdividef(num.x, den.x) : 0.f;
    o.y = (den.y > 0.f) ? __fdividef(num.y, den.y) : 0.f;
    o.z = (den.z > 0.f) ? __fdividef(num.z, den.z) : 0.f;
    o.w = (den.w > 0.f) ? __fdividef(num.w, den.w) : 0.f;
    *(float4*)&out[d * 128 + lane * 4] = o;
}

// ---------------- launch ----------------
extern "C" void kernel_launch(void* const* d_in, const int* in_sizes, int n_in,
                              void* d_out, int out_size)
{
    const float* node_feats = (const float*)d_in[0];
    const float* edge_feats = (const float*)d_in[1];
    const int*   src        = (const int*)d_in[2];
    const int*   dst        = (const int*)d_in[3];
    const float* W          = (const float*)d_in[4];
    const float* b          = (const float*)d_in[5];
    const float* attn_v     = (const float*)d_in[6];
    const float* Wres       = (const float*)d_in[7];
    const float* bres       = (const float*)d_in[8];
    const float* We         = (const float*)d_in[9];
    const float* be         = (const float*)d_in[10];
    float* out = (float*)d_out;

    cudaFuncSetAttribute(k_node_gemm, cudaFuncAttributeMaxDynamicSharedMemorySize, NODE_SMEM);
    cudaFuncSetAttribute(k_edge_gemm, cudaFuncAttributeMaxDynamicSharedMemorySize, EDGE_SMEM);

    int nodeBlocks = (NN + 255) / 256;         // 196
    int edgeBlocks = (EE + 255) / 256;         // 2344
    int warpNodeBlocks = (NN + 7) / 8;         // 6250 (warp per dst)

    // Order: k_node_gemm at our launch index 3 -> ncu -s 5 capture target.
    k_zero<<<nodeBlocks, 256>>>();
    k_hist<<<edgeBlocks, 256>>>(dst);
    k_scan<<<1, 1024>>>();
    k_node_gemm<<<148, 256, NODE_SMEM>>>(node_feats, W, b, Wres, bres);
    k_fill<<<edgeBlocks, 256>>>(dst);
    k_score_gather<<<warpNodeBlocks, 256>>>(src, attn_v);
    k_edge_gemm<<<592, 256, EDGE_SMEM>>>(edge_feats, We, be, src);
    k_mail_gather<<<warpNodeBlocks, 256>>>(out);
}